// round 1
// baseline (speedup 1.0000x reference)
#include <cuda_runtime.h>
#include <cuda_bf16.h>

#define N_NODES  50000
#define N_EDGES  600000
#define BAG      16
#define EMB      128
#define HID      128
#define N_GRAPHS 512
#define N_CLS    10
#define PAD_IDX  1

#define TM 64
#define TK 32

// ---------------- scratch (static device globals; no allocation) ------------
__device__ __align__(16) float g_x0 [N_NODES * HID];   // embed out / layer2 out
__device__ __align__(16) float g_h1 [N_NODES * HID];   // layer1 out
__device__ __align__(16) float g_agg[N_NODES * HID];   // scatter accumulator
__device__ __align__(16) float g_deg[N_NODES];
__device__ __align__(16) float g_inv[N_NODES];
__device__ __align__(16) float g_gsum[N_GRAPHS * HID];
__device__ __align__(16) float g_gcnt[N_GRAPHS];
__device__ __align__(16) float g_wc1[256 * 128];       // [k(256)][o(128)] combined W
__device__ __align__(16) float g_wc2[256 * 128];

__device__ __forceinline__ void red_add_v4(float* p, float4 v) {
    asm volatile("red.global.add.v4.f32 [%0], {%1,%2,%3,%4};"
                 :: "l"(p), "f"(v.x), "f"(v.y), "f"(v.z), "f"(v.w) : "memory");
}

// ---------------- zeroing ---------------------------------------------------
__global__ void k_zero_pre() {
    int t = blockIdx.x * blockDim.x + threadIdx.x;
    int stride = gridDim.x * blockDim.x;
    float4 z = make_float4(0.f, 0.f, 0.f, 0.f);
    for (int i = t; i < N_NODES * HID / 4; i += stride)
        ((float4*)g_agg)[i] = z;
    for (int i = t; i < N_NODES; i += stride) g_deg[i] = 0.f;
    for (int i = t; i < N_GRAPHS; i += stride) g_gcnt[i] = 0.f;
    for (int i = t; i < N_GRAPHS * HID; i += stride) g_gsum[i] = 0.f;
}

__global__ void k_zero_agg() {
    int t = blockIdx.x * blockDim.x + threadIdx.x;
    int stride = gridDim.x * blockDim.x;
    float4 z = make_float4(0.f, 0.f, 0.f, 0.f);
    for (int i = t; i < N_NODES * HID / 4; i += stride)
        ((float4*)g_agg)[i] = z;
}

// ---------------- embedding bag (mean, pad-excluded count) ------------------
__global__ void k_embed(const int* __restrict__ tokens,
                        const float* __restrict__ table) {
    int w = (blockIdx.x * blockDim.x + threadIdx.x) >> 5;
    int lane = threadIdx.x & 31;
    if (w >= N_NODES) return;
    const int* tk = tokens + w * BAG;
    float4 acc = make_float4(0.f, 0.f, 0.f, 0.f);
    int cnt = 0;
#pragma unroll
    for (int t = 0; t < BAG; t++) {
        int tok = tk[t];                 // uniform per warp -> broadcast load
        if (tok != PAD_IDX) {
            cnt++;
            float4 e = *(const float4*)(table + (size_t)tok * EMB + lane * 4);
            acc.x += e.x; acc.y += e.y; acc.z += e.z; acc.w += e.w;
        }
    }
    float inv = 1.0f / (float)max(cnt, 1);
    acc.x *= inv; acc.y *= inv; acc.z *= inv; acc.w *= inv;
    *(float4*)(g_x0 + (size_t)w * HID + lane * 4) = acc;
}

// ---------------- degree + graph counts -------------------------------------
__global__ void k_counts(const int* __restrict__ dst, const int* __restrict__ batch) {
    int i = blockIdx.x * blockDim.x + threadIdx.x;
    if (i < N_EDGES) atomicAdd(&g_deg[dst[i]], 1.0f);
    if (i < N_NODES) atomicAdd(&g_gcnt[batch[i]], 1.0f);
}

__global__ void k_invdeg() {
    int i = blockIdx.x * blockDim.x + threadIdx.x;
    if (i < N_NODES) g_inv[i] = 1.0f / fmaxf(g_deg[i], 1.0f);
}

// ---------------- build combined weights  Wc[k][o] = k<128 ? wl[o][k] : wr[o][k-128]
__global__ void k_prepw(const float* __restrict__ w1l, const float* __restrict__ w1r,
                        const float* __restrict__ w2l, const float* __restrict__ w2r) {
    int i = blockIdx.x * blockDim.x + threadIdx.x;
    if (i >= 256 * 128) return;
    int k = i >> 7, o = i & 127;
    g_wc1[i] = (k < 128) ? w1l[o * 128 + k] : w1r[o * 128 + (k - 128)];
    g_wc2[i] = (k < 128) ? w2l[o * 128 + k] : w2r[o * 128 + (k - 128)];
}

// ---------------- edge scatter: agg[dst] += x[src]  (one warp per edge) -----
__global__ void k_scatter(const int* __restrict__ src, const int* __restrict__ dst,
                          int phase) {
    const float* __restrict__ x = phase ? g_h1 : g_x0;
    int e = (blockIdx.x * blockDim.x + threadIdx.x) >> 5;
    int lane = threadIdx.x & 31;
    if (e >= N_EDGES) return;
    int s = src[e], d = dst[e];
    float4 v = *(const float4*)(x + (size_t)s * HID + lane * 4);
    red_add_v4(g_agg + (size_t)d * HID + lane * 4, v);
}

// ---------------- fused dual GEMM + bias + relu -----------------------------
// out[n][o] = relu( sum_k  A(n,k) * Wc[k][o]  + b[o] ),  A = [agg*inv | x], K=256
__global__ __launch_bounds__(256) void k_mm(int phase, const float* __restrict__ bias) {
    const float* __restrict__ xin = phase ? g_h1 : g_x0;
    const float* __restrict__ wc  = phase ? g_wc2 : g_wc1;
    float* __restrict__ out       = phase ? g_x0 : g_h1;

    __shared__ float As[TK][TM + 4];
    __shared__ float Bs[TK][128];

    int tid = threadIdx.x;
    int tx = tid & 31, ty = tid >> 5;
    int row0 = blockIdx.x * TM;

    float acc[8][4];
#pragma unroll
    for (int j = 0; j < 8; j++)
#pragma unroll
        for (int c = 0; c < 4; c++) acc[j][c] = 0.f;

    for (int kt = 0; kt < 8; kt++) {
        int k0 = kt * TK;
        bool is_agg = (k0 < 128);
        const float* srcA = is_agg ? g_agg : xin;
        int kbase = k0 & 127;
        // load A tile (64x32), transposed into As[k][row]
#pragma unroll
        for (int i = 0; i < 2; i++) {
            int f4 = tid + i * 256;
            int r  = f4 >> 3;        // 0..63
            int kq = f4 & 7;         // 0..7
            int rg = row0 + r;
            float4 v = make_float4(0.f, 0.f, 0.f, 0.f);
            if (rg < N_NODES) {
                v = *(const float4*)(srcA + (size_t)rg * 128 + kbase + kq * 4);
                if (is_agg) {
                    float inv = g_inv[rg];
                    v.x *= inv; v.y *= inv; v.z *= inv; v.w *= inv;
                }
            }
            As[kq * 4 + 0][r] = v.x;
            As[kq * 4 + 1][r] = v.y;
            As[kq * 4 + 2][r] = v.z;
            As[kq * 4 + 3][r] = v.w;
        }
        // load B tile (32x128)
#pragma unroll
        for (int i = 0; i < 4; i++) {
            int f4 = tid + i * 256;
            int br = f4 >> 5;        // 0..31
            int bc = f4 & 31;        // 0..31
            *(float4*)&Bs[br][bc * 4] =
                *(const float4*)(wc + (size_t)(k0 + br) * 128 + bc * 4);
        }
        __syncthreads();
#pragma unroll
        for (int kk = 0; kk < TK; kk++) {
            float4 a0 = *(float4*)&As[kk][ty * 8];
            float4 a1 = *(float4*)&As[kk][ty * 8 + 4];
            float4 b  = *(float4*)&Bs[kk][tx * 4];
            float av[8] = {a0.x, a0.y, a0.z, a0.w, a1.x, a1.y, a1.z, a1.w};
            float bv[4] = {b.x, b.y, b.z, b.w};
#pragma unroll
            for (int j = 0; j < 8; j++)
#pragma unroll
                for (int c = 0; c < 4; c++)
                    acc[j][c] += av[j] * bv[c];
        }
        __syncthreads();
    }

    float4 bb = *(const float4*)(bias + tx * 4);
#pragma unroll
    for (int j = 0; j < 8; j++) {
        int rg = row0 + ty * 8 + j;
        if (rg < N_NODES) {
            float4 o;
            o.x = fmaxf(acc[j][0] + bb.x, 0.f);
            o.y = fmaxf(acc[j][1] + bb.y, 0.f);
            o.z = fmaxf(acc[j][2] + bb.z, 0.f);
            o.w = fmaxf(acc[j][3] + bb.w, 0.f);
            *(float4*)(out + (size_t)rg * 128 + tx * 4) = o;
        }
    }
}

// ---------------- global mean pool (sum via red.v4) -------------------------
__global__ void k_pool(const int* __restrict__ batch) {
    int w = (blockIdx.x * blockDim.x + threadIdx.x) >> 5;
    int lane = threadIdx.x & 31;
    if (w >= N_NODES) return;
    int g = batch[w];                // uniform per warp
    float4 v = *(const float4*)(g_x0 + (size_t)w * HID + lane * 4);
    red_add_v4(g_gsum + (size_t)g * HID + lane * 4, v);
}

// ---------------- final linear head -----------------------------------------
__global__ void k_out(const float* __restrict__ wout, const float* __restrict__ bout,
                      float* __restrict__ y) {
    int g = blockIdx.x;
    __shared__ float row[128];
    float inv = 1.0f / fmaxf(g_gcnt[g], 1.0f);
    row[threadIdx.x] = g_gsum[g * 128 + threadIdx.x] * inv;
    __syncthreads();
    if (threadIdx.x < N_CLS) {
        float s = bout[threadIdx.x];
        const float* wrow = wout + threadIdx.x * 128;
#pragma unroll 16
        for (int d = 0; d < 128; d++) s += row[d] * wrow[d];
        y[g * N_CLS + threadIdx.x] = s;
    }
}

// ---------------- launch -----------------------------------------------------
extern "C" void kernel_launch(void* const* d_in, const int* in_sizes, int n_in,
                              void* d_out, int out_size) {
    const int*   x_tokens = (const int*)  d_in[0];
    const int*   ei       = (const int*)  d_in[1];
    const int*   batch    = (const int*)  d_in[2];
    const float* emb      = (const float*)d_in[3];
    const float* w1l      = (const float*)d_in[4];
    const float* b1       = (const float*)d_in[5];
    const float* w1r      = (const float*)d_in[6];
    const float* w2l      = (const float*)d_in[7];
    const float* b2       = (const float*)d_in[8];
    const float* w2r      = (const float*)d_in[9];
    const float* wout     = (const float*)d_in[10];
    const float* bout     = (const float*)d_in[11];
    float* y = (float*)d_out;

    const int* src = ei;
    const int* dst = ei + N_EDGES;

    k_zero_pre<<<2048, 256>>>();
    k_embed  <<<(N_NODES * 32 + 255) / 256, 256>>>(x_tokens, emb);
    k_counts <<<(N_EDGES + 255) / 256, 256>>>(dst, batch);
    k_invdeg <<<(N_NODES + 255) / 256, 256>>>();
    k_prepw  <<<(256 * 128 + 255) / 256, 256>>>(w1l, w1r, w2l, w2r);

    k_scatter<<<(N_EDGES * 32 + 255) / 256, 256>>>(src, dst, 0);
    k_mm     <<<(N_NODES + TM - 1) / TM, 256>>>(0, b1);

    k_zero_agg<<<2048, 256>>>();
    k_scatter<<<(N_EDGES * 32 + 255) / 256, 256>>>(src, dst, 1);
    k_mm     <<<(N_NODES + TM - 1) / TM, 256>>>(1, b2);

    k_pool   <<<(N_NODES * 32 + 255) / 256, 256>>>(batch);
    k_out    <<<N_GRAPHS, 128>>>(wout, bout, y);
}

// round 2
// speedup vs baseline: 1.2586x; 1.2586x over previous
#include <cuda_runtime.h>
#include <cuda_bf16.h>

#define N_NODES  50000
#define N_EDGES  600000
#define BAG      16
#define EMB      128
#define HID      128
#define N_GRAPHS 512
#define N_CLS    10
#define PAD_IDX  1

#define TM 64
#define TK 32
#define NBLK 196   // ceil(N_NODES/256)

typedef unsigned long long ull;

// ---------------- scratch (static device globals; no allocation) ------------
__device__ __align__(16) float g_x0 [N_NODES * HID];   // embed out / layer2 out
__device__ __align__(16) float g_h1 [N_NODES * HID];   // layer1 out
__device__ __align__(16) float g_agg[N_NODES * HID];   // gathered+scaled neighbor mean
__device__ __align__(16) float g_gsum[N_GRAPHS * HID];
__device__ __align__(16) float g_gcnt[N_GRAPHS];
__device__ __align__(16) float g_wc1[256 * 128];       // [k(256)][o(128)] combined W
__device__ __align__(16) float g_wc2[256 * 128];
// CSR
__device__ int g_degi  [N_NODES];
__device__ int g_offs  [N_NODES];
__device__ int g_cursor[N_NODES];
__device__ int g_adj   [N_EDGES];
__device__ int g_bsum  [256];
__device__ int g_bbase [256];

__device__ __forceinline__ void red_add_v4(float* p, float4 v) {
    asm volatile("red.global.add.v4.f32 [%0], {%1,%2,%3,%4};"
                 :: "l"(p), "f"(v.x), "f"(v.y), "f"(v.z), "f"(v.w) : "memory");
}
__device__ __forceinline__ ull pack2(float x) {
    ull r; asm("mov.b64 %0, {%1, %1};" : "=l"(r) : "f"(x)); return r;
}
__device__ __forceinline__ void unpack2(ull v, float& lo, float& hi) {
    asm("mov.b64 {%0, %1}, %2;" : "=f"(lo), "=f"(hi) : "l"(v));
}
__device__ __forceinline__ void ffma2(ull& d, ull a, ull b) {
    asm("fma.rn.f32x2 %0, %1, %2, %0;" : "+l"(d) : "l"(a), "l"(b));
}

// ---------------- zeroing ---------------------------------------------------
__global__ void k_zero_pre() {
    int t = blockIdx.x * blockDim.x + threadIdx.x;
    int stride = gridDim.x * blockDim.x;
    for (int i = t; i < N_NODES; i += stride) { g_degi[i] = 0; g_cursor[i] = 0; }
    for (int i = t; i < N_GRAPHS; i += stride) g_gcnt[i] = 0.f;
    for (int i = t; i < N_GRAPHS * HID; i += stride) g_gsum[i] = 0.f;
}

// ---------------- embedding bag (mean, pad-excluded count) ------------------
__global__ void k_embed(const int* __restrict__ tokens,
                        const float* __restrict__ table) {
    int w = (blockIdx.x * blockDim.x + threadIdx.x) >> 5;
    int lane = threadIdx.x & 31;
    if (w >= N_NODES) return;
    const int* tk = tokens + w * BAG;
    float4 acc = make_float4(0.f, 0.f, 0.f, 0.f);
    int cnt = 0;
#pragma unroll
    for (int t = 0; t < BAG; t++) {
        int tok = tk[t];                 // uniform per warp -> broadcast load
        if (tok != PAD_IDX) {
            cnt++;
            float4 e = *(const float4*)(table + (size_t)tok * EMB + lane * 4);
            acc.x += e.x; acc.y += e.y; acc.z += e.z; acc.w += e.w;
        }
    }
    float inv = 1.0f / (float)max(cnt, 1);
    acc.x *= inv; acc.y *= inv; acc.z *= inv; acc.w *= inv;
    *(float4*)(g_x0 + (size_t)w * HID + lane * 4) = acc;
}

// ---------------- degree (int) + graph counts -------------------------------
__global__ void k_counts(const int* __restrict__ dst, const int* __restrict__ batch) {
    int i = blockIdx.x * blockDim.x + threadIdx.x;
    if (i < N_EDGES) atomicAdd(&g_degi[dst[i]], 1);
    if (i < N_NODES) atomicAdd(&g_gcnt[batch[i]], 1.0f);
}

// ---------------- 3-step exclusive scan of g_degi -> g_offs ------------------
__global__ void k_scan_a() {   // per-block sums
    __shared__ int s[256];
    int t = threadIdx.x, i = blockIdx.x * 256 + t;
    int v = (i < N_NODES) ? g_degi[i] : 0;
    s[t] = v; __syncthreads();
#pragma unroll
    for (int o = 128; o > 0; o >>= 1) {
        if (t < o) s[t] += s[t + o];
        __syncthreads();
    }
    if (t == 0) g_bsum[blockIdx.x] = s[0];
}
__global__ void k_scan_b() {   // scan block sums (1 block, 256 threads)
    __shared__ int s[256];
    int t = threadIdx.x;
    int v = (t < NBLK) ? g_bsum[t] : 0;
    s[t] = v; __syncthreads();
#pragma unroll
    for (int o = 1; o < 256; o <<= 1) {
        int x = (t >= o) ? s[t - o] : 0;
        __syncthreads();
        s[t] += x;
        __syncthreads();
    }
    g_bbase[t] = s[t] - v;     // exclusive
}
__global__ void k_scan_c() {   // intra-block scan + base
    __shared__ int s[256];
    int t = threadIdx.x, i = blockIdx.x * 256 + t;
    int v = (i < N_NODES) ? g_degi[i] : 0;
    s[t] = v; __syncthreads();
#pragma unroll
    for (int o = 1; o < 256; o <<= 1) {
        int x = (t >= o) ? s[t - o] : 0;
        __syncthreads();
        s[t] += x;
        __syncthreads();
    }
    if (i < N_NODES) g_offs[i] = g_bbase[blockIdx.x] + s[t] - v;
}

// ---------------- CSR fill ---------------------------------------------------
__global__ void k_fill(const int* __restrict__ src, const int* __restrict__ dst) {
    int i = blockIdx.x * blockDim.x + threadIdx.x;
    if (i >= N_EDGES) return;
    int d = dst[i];
    int pos = atomicAdd(&g_cursor[d], 1);
    g_adj[g_offs[d] + pos] = src[i];
}

// ---------------- build combined weights  Wc[k][o] = k<128 ? wl[o][k] : wr[o][k-128]
__global__ void k_prepw(const float* __restrict__ w1l, const float* __restrict__ w1r,
                        const float* __restrict__ w2l, const float* __restrict__ w2r) {
    int i = blockIdx.x * blockDim.x + threadIdx.x;
    if (i >= 256 * 128) return;
    int k = i >> 7, o = i & 127;
    g_wc1[i] = (k < 128) ? w1l[o * 128 + k] : w1r[o * 128 + (k - 128)];
    g_wc2[i] = (k < 128) ? w2l[o * 128 + k] : w2r[o * 128 + (k - 128)];
}

// ---------------- gather aggregation: agg[n] = mean_{s in N(n)} x[s] --------
__global__ void k_gather(int phase) {
    const float* __restrict__ x = phase ? g_h1 : g_x0;
    int w = (blockIdx.x * blockDim.x + threadIdx.x) >> 5;
    int lane = threadIdx.x & 31;
    if (w >= N_NODES) return;
    int beg = g_offs[w];
    int d   = g_degi[w];
    float4 acc0 = make_float4(0.f, 0.f, 0.f, 0.f);
    float4 acc1 = make_float4(0.f, 0.f, 0.f, 0.f);
    int i = 0;
    for (; i + 2 <= d; i += 2) {
        int s0 = g_adj[beg + i], s1 = g_adj[beg + i + 1];
        float4 v0 = *(const float4*)(x + (size_t)s0 * HID + lane * 4);
        float4 v1 = *(const float4*)(x + (size_t)s1 * HID + lane * 4);
        acc0.x += v0.x; acc0.y += v0.y; acc0.z += v0.z; acc0.w += v0.w;
        acc1.x += v1.x; acc1.y += v1.y; acc1.z += v1.z; acc1.w += v1.w;
    }
    if (i < d) {
        int s0 = g_adj[beg + i];
        float4 v0 = *(const float4*)(x + (size_t)s0 * HID + lane * 4);
        acc0.x += v0.x; acc0.y += v0.y; acc0.z += v0.z; acc0.w += v0.w;
    }
    float inv = 1.0f / (float)max(d, 1);
    float4 o;
    o.x = (acc0.x + acc1.x) * inv;
    o.y = (acc0.y + acc1.y) * inv;
    o.z = (acc0.z + acc1.z) * inv;
    o.w = (acc0.w + acc1.w) * inv;
    *(float4*)(g_agg + (size_t)w * HID + lane * 4) = o;
}

// ---------------- fused dual GEMM + bias + relu (f32x2 packed FMA) ----------
// out[n][o] = relu( sum_k  A(n,k) * Wc[k][o]  + b[o] ),  A = [agg | x], K=256
__global__ __launch_bounds__(256) void k_mm(int phase, const float* __restrict__ bias) {
    const float* __restrict__ xin = phase ? g_h1 : g_x0;
    const float* __restrict__ wc  = phase ? g_wc2 : g_wc1;
    float* __restrict__ out       = phase ? g_x0 : g_h1;

    __shared__ float As[TK][TM + 4];
    __shared__ float Bs[TK][128];

    int tid = threadIdx.x;
    int tx = tid & 31, ty = tid >> 5;
    int row0 = blockIdx.x * TM;

    // acc2[j2][c]: lo = row (ty*8 + 2*j2), hi = row (ty*8 + 2*j2 + 1), col tx*4+c
    ull acc2[4][4];
#pragma unroll
    for (int j = 0; j < 4; j++)
#pragma unroll
        for (int c = 0; c < 4; c++) acc2[j][c] = 0ull;

    for (int kt = 0; kt < 8; kt++) {
        int k0 = kt * TK;
        const float* srcA = (k0 < 128) ? g_agg : xin;
        int kbase = k0 & 127;
        // load A tile (64x32), transposed into As[k][row]
#pragma unroll
        for (int i = 0; i < 2; i++) {
            int f4 = tid + i * 256;
            int r  = f4 >> 3;        // 0..63
            int kq = f4 & 7;         // 0..7
            int rg = row0 + r;
            float4 v = make_float4(0.f, 0.f, 0.f, 0.f);
            if (rg < N_NODES)
                v = *(const float4*)(srcA + (size_t)rg * 128 + kbase + kq * 4);
            As[kq * 4 + 0][r] = v.x;
            As[kq * 4 + 1][r] = v.y;
            As[kq * 4 + 2][r] = v.z;
            As[kq * 4 + 3][r] = v.w;
        }
        // load B tile (32x128)
#pragma unroll
        for (int i = 0; i < 4; i++) {
            int f4 = tid + i * 256;
            int br = f4 >> 5;        // 0..31
            int bc = f4 & 31;        // 0..31
            *(float4*)&Bs[br][bc * 4] =
                *(const float4*)(wc + (size_t)(k0 + br) * 128 + bc * 4);
        }
        __syncthreads();
#pragma unroll
        for (int kk = 0; kk < TK; kk++) {
            const ull* ap = (const ull*)&As[kk][ty * 8];    // 4 row-pairs
            float4 b = *(float4*)&Bs[kk][tx * 4];
            ull bp0 = pack2(b.x), bp1 = pack2(b.y), bp2 = pack2(b.z), bp3 = pack2(b.w);
#pragma unroll
            for (int j = 0; j < 4; j++) {
                ull a = ap[j];
                ffma2(acc2[j][0], a, bp0);
                ffma2(acc2[j][1], a, bp1);
                ffma2(acc2[j][2], a, bp2);
                ffma2(acc2[j][3], a, bp3);
            }
        }
        __syncthreads();
    }

    float4 bb = *(const float4*)(bias + tx * 4);
    float bbv[4] = {bb.x, bb.y, bb.z, bb.w};
#pragma unroll
    for (int j = 0; j < 4; j++) {
        int r0 = row0 + ty * 8 + 2 * j;
        float lo[4], hi[4];
#pragma unroll
        for (int c = 0; c < 4; c++) unpack2(acc2[j][c], lo[c], hi[c]);
        if (r0 < N_NODES) {
            float4 o;
            o.x = fmaxf(lo[0] + bbv[0], 0.f);
            o.y = fmaxf(lo[1] + bbv[1], 0.f);
            o.z = fmaxf(lo[2] + bbv[2], 0.f);
            o.w = fmaxf(lo[3] + bbv[3], 0.f);
            *(float4*)(out + (size_t)r0 * 128 + tx * 4) = o;
        }
        if (r0 + 1 < N_NODES) {
            float4 o;
            o.x = fmaxf(hi[0] + bbv[0], 0.f);
            o.y = fmaxf(hi[1] + bbv[1], 0.f);
            o.z = fmaxf(hi[2] + bbv[2], 0.f);
            o.w = fmaxf(hi[3] + bbv[3], 0.f);
            *(float4*)(out + (size_t)(r0 + 1) * 128 + tx * 4) = o;
        }
    }
}

// ---------------- global mean pool (sum via red.v4) -------------------------
__global__ void k_pool(const int* __restrict__ batch) {
    int w = (blockIdx.x * blockDim.x + threadIdx.x) >> 5;
    int lane = threadIdx.x & 31;
    if (w >= N_NODES) return;
    int g = batch[w];                // uniform per warp
    float4 v = *(const float4*)(g_x0 + (size_t)w * HID + lane * 4);
    red_add_v4(g_gsum + (size_t)g * HID + lane * 4, v);
}

// ---------------- final linear head -----------------------------------------
__global__ void k_out(const float* __restrict__ wout, const float* __restrict__ bout,
                      float* __restrict__ y) {
    int g = blockIdx.x;
    __shared__ float row[128];
    float inv = 1.0f / fmaxf(g_gcnt[g], 1.0f);
    row[threadIdx.x] = g_gsum[g * 128 + threadIdx.x] * inv;
    __syncthreads();
    if (threadIdx.x < N_CLS) {
        float s = bout[threadIdx.x];
        const float* wrow = wout + threadIdx.x * 128;
#pragma unroll 16
        for (int d = 0; d < 128; d++) s += row[d] * wrow[d];
        y[g * N_CLS + threadIdx.x] = s;
    }
}

// ---------------- launch -----------------------------------------------------
extern "C" void kernel_launch(void* const* d_in, const int* in_sizes, int n_in,
                              void* d_out, int out_size) {
    const int*   x_tokens = (const int*)  d_in[0];
    const int*   ei       = (const int*)  d_in[1];
    const int*   batch    = (const int*)  d_in[2];
    const float* emb      = (const float*)d_in[3];
    const float* w1l      = (const float*)d_in[4];
    const float* b1       = (const float*)d_in[5];
    const float* w1r      = (const float*)d_in[6];
    const float* w2l      = (const float*)d_in[7];
    const float* b2       = (const float*)d_in[8];
    const float* w2r      = (const float*)d_in[9];
    const float* wout     = (const float*)d_in[10];
    const float* bout     = (const float*)d_in[11];
    float* y = (float*)d_out;

    const int* src = ei;
    const int* dst = ei + N_EDGES;

    k_zero_pre<<<512, 256>>>();
    k_embed  <<<(N_NODES * 32 + 255) / 256, 256>>>(x_tokens, emb);
    k_counts <<<(N_EDGES + 255) / 256, 256>>>(dst, batch);
    k_scan_a <<<NBLK, 256>>>();
    k_scan_b <<<1, 256>>>();
    k_scan_c <<<NBLK, 256>>>();
    k_fill   <<<(N_EDGES + 255) / 256, 256>>>(src, dst);
    k_prepw  <<<(256 * 128 + 255) / 256, 256>>>(w1l, w1r, w2l, w2r);

    k_gather <<<(N_NODES * 32 + 255) / 256, 256>>>(0);
    k_mm     <<<(N_NODES + TM - 1) / TM, 256>>>(0, b1);

    k_gather <<<(N_NODES * 32 + 255) / 256, 256>>>(1);
    k_mm     <<<(N_NODES + TM - 1) / TM, 256>>>(1, b2);

    k_pool   <<<(N_NODES * 32 + 255) / 256, 256>>>(batch);
    k_out    <<<N_GRAPHS, 128>>>(wout, bout, y);
}

// round 6
// speedup vs baseline: 1.6130x; 1.2816x over previous
#include <cuda_runtime.h>
#include <cuda_bf16.h>
#include <cstdint>

#define N_NODES  50000
#define N_EDGES  600000
#define BAG      16
#define EMB      128
#define HID      128
#define N_GRAPHS 512
#define N_CLS    10
#define PAD_IDX  1
#define NBLK 196   // ceil(N_NODES/256)

typedef unsigned long long ull;

// ---------------- scratch (static device globals; no allocation) ------------
__device__ __align__(16) float g_x0 [N_NODES * HID];   // embed out / layer2 out
__device__ __align__(16) float g_h1 [N_NODES * HID];   // layer1 out
__device__ __align__(16) float g_agg[N_NODES * HID];   // gathered neighbor mean
__device__ __align__(16) float g_gsum[N_GRAPHS * HID];
__device__ __align__(16) float g_gcnt[N_GRAPHS];
// CSR
__device__ int g_degi  [N_NODES];
__device__ int g_offs  [N_NODES];
__device__ int g_cursor[N_NODES];
__device__ int g_adj   [N_EDGES];
__device__ int g_bsum  [256];
__device__ int g_bbase [256];

// ---------------- PTX helpers -----------------------------------------------
__device__ __forceinline__ void red_add_v4(float* p, float4 v) {
    asm volatile("red.global.add.v4.f32 [%0], {%1,%2,%3,%4};"
                 :: "l"(p), "f"(v.x), "f"(v.y), "f"(v.z), "f"(v.w) : "memory");
}
__device__ __forceinline__ float f2tf32f(float x) {
    uint32_t r; asm("cvt.rna.tf32.f32 %0, %1;" : "=r"(r) : "f"(x));
    return __uint_as_float(r);
}
__device__ __forceinline__ void mma_tf32(float* c, const uint32_t* a, const uint32_t* b) {
    asm volatile("mma.sync.aligned.m16n8k8.row.col.f32.tf32.tf32.f32 "
        "{%0,%1,%2,%3}, {%4,%5,%6,%7}, {%8,%9}, {%0,%1,%2,%3};"
        : "+f"(c[0]), "+f"(c[1]), "+f"(c[2]), "+f"(c[3])
        : "r"(a[0]), "r"(a[1]), "r"(a[2]), "r"(a[3]), "r"(b[0]), "r"(b[1]));
}

// ---------------- zeroing ---------------------------------------------------
__global__ void k_zero_pre() {
    int t = blockIdx.x * blockDim.x + threadIdx.x;
    int stride = gridDim.x * blockDim.x;
    for (int i = t; i < N_NODES; i += stride) { g_degi[i] = 0; g_cursor[i] = 0; }
    for (int i = t; i < N_GRAPHS; i += stride) g_gcnt[i] = 0.f;
    for (int i = t; i < N_GRAPHS * HID; i += stride) g_gsum[i] = 0.f;
}

// ---------------- embedding bag (mean, pad-excluded count) ------------------
__global__ void k_embed(const int* __restrict__ tokens,
                        const float* __restrict__ table) {
    int w = (blockIdx.x * blockDim.x + threadIdx.x) >> 5;
    int lane = threadIdx.x & 31;
    if (w >= N_NODES) return;
    const int* tk = tokens + w * BAG;
    float4 acc = make_float4(0.f, 0.f, 0.f, 0.f);
    int cnt = 0;
#pragma unroll
    for (int t = 0; t < BAG; t++) {
        int tok = tk[t];
        if (tok != PAD_IDX) {
            cnt++;
            float4 e = *(const float4*)(table + (size_t)tok * EMB + lane * 4);
            acc.x += e.x; acc.y += e.y; acc.z += e.z; acc.w += e.w;
        }
    }
    float inv = 1.0f / (float)max(cnt, 1);
    acc.x *= inv; acc.y *= inv; acc.z *= inv; acc.w *= inv;
    *(float4*)(g_x0 + (size_t)w * HID + lane * 4) = acc;
}

// ---------------- degree (int) + graph counts -------------------------------
__global__ void k_counts(const int* __restrict__ dst, const int* __restrict__ batch) {
    int i = blockIdx.x * blockDim.x + threadIdx.x;
    if (i < N_EDGES) atomicAdd(&g_degi[dst[i]], 1);
    if (i < N_NODES) atomicAdd(&g_gcnt[batch[i]], 1.0f);
}

// ---------------- 3-step exclusive scan of g_degi -> g_offs ------------------
__global__ void k_scan_a() {
    __shared__ int s[256];
    int t = threadIdx.x, i = blockIdx.x * 256 + t;
    int v = (i < N_NODES) ? g_degi[i] : 0;
    s[t] = v; __syncthreads();
#pragma unroll
    for (int o = 128; o > 0; o >>= 1) {
        if (t < o) s[t] += s[t + o];
        __syncthreads();
    }
    if (t == 0) g_bsum[blockIdx.x] = s[0];
}
__global__ void k_scan_b() {
    __shared__ int s[256];
    int t = threadIdx.x;
    int v = (t < NBLK) ? g_bsum[t] : 0;
    s[t] = v; __syncthreads();
#pragma unroll
    for (int o = 1; o < 256; o <<= 1) {
        int x = (t >= o) ? s[t - o] : 0;
        __syncthreads();
        s[t] += x;
        __syncthreads();
    }
    g_bbase[t] = s[t] - v;
}
__global__ void k_scan_c() {
    __shared__ int s[256];
    int t = threadIdx.x, i = blockIdx.x * 256 + t;
    int v = (i < N_NODES) ? g_degi[i] : 0;
    s[t] = v; __syncthreads();
#pragma unroll
    for (int o = 1; o < 256; o <<= 1) {
        int x = (t >= o) ? s[t - o] : 0;
        __syncthreads();
        s[t] += x;
        __syncthreads();
    }
    if (i < N_NODES) g_offs[i] = g_bbase[blockIdx.x] + s[t] - v;
}

// ---------------- CSR fill ---------------------------------------------------
__global__ void k_fill(const int* __restrict__ src, const int* __restrict__ dst) {
    int i = blockIdx.x * blockDim.x + threadIdx.x;
    if (i >= N_EDGES) return;
    int d = dst[i];
    int pos = atomicAdd(&g_cursor[d], 1);
    g_adj[g_offs[d] + pos] = src[i];
}

// ---------------- gather aggregation: agg[n] = mean_{s in N(n)} x[s] --------
__global__ void k_gather(int phase) {
    const float* __restrict__ x = phase ? g_h1 : g_x0;
    int w = (blockIdx.x * blockDim.x + threadIdx.x) >> 5;
    int lane = threadIdx.x & 31;
    if (w >= N_NODES) return;
    int beg = g_offs[w];
    int d   = g_degi[w];
    float4 acc0 = make_float4(0.f, 0.f, 0.f, 0.f);
    float4 acc1 = make_float4(0.f, 0.f, 0.f, 0.f);
    int i = 0;
    for (; i + 2 <= d; i += 2) {
        int s0 = g_adj[beg + i], s1 = g_adj[beg + i + 1];
        float4 v0 = *(const float4*)(x + (size_t)s0 * HID + lane * 4);
        float4 v1 = *(const float4*)(x + (size_t)s1 * HID + lane * 4);
        acc0.x += v0.x; acc0.y += v0.y; acc0.z += v0.z; acc0.w += v0.w;
        acc1.x += v1.x; acc1.y += v1.y; acc1.z += v1.z; acc1.w += v1.w;
    }
    if (i < d) {
        int s0 = g_adj[beg + i];
        float4 v0 = *(const float4*)(x + (size_t)s0 * HID + lane * 4);
        acc0.x += v0.x; acc0.y += v0.y; acc0.z += v0.z; acc0.w += v0.w;
    }
    float inv = 1.0f / (float)max(d, 1);
    float4 o;
    o.x = (acc0.x + acc1.x) * inv;
    o.y = (acc0.y + acc1.y) * inv;
    o.z = (acc0.z + acc1.z) * inv;
    o.w = (acc0.w + acc1.w) * inv;
    *(float4*)(g_agg + (size_t)w * HID + lane * 4) = o;
}

// ---------------- tf32 mma.sync fused dual GEMM + bias + relu ---------------
// out[row][o] = relu( [agg | xin] @ [wl | wr]^T + bias ), K=256, 128x128 CTA tile
// smem: sA[8][8][32][4] fragments (32KB), sB[16][8][32][2] (32KB), bias (512B)
#define MM_SMEM (65536 + 512)

__global__ __launch_bounds__(256) void k_mm_mma(const float* __restrict__ xin,
                                                const float* __restrict__ wl,
                                                const float* __restrict__ wr,
                                                const float* __restrict__ bias,
                                                float* __restrict__ out) {
    extern __shared__ float sm[];
    float* sA = sm;                 // A fragments
    float* sB = sm + 8192;          // B fragments
    float* sBias = sm + 16384;
    int tid = threadIdx.x;
    int lane = tid & 31, wid = tid >> 5;
    int warp_m = wid & 1;           // 2 warps over M (64 rows each)
    int warp_n = wid >> 1;          // 4 warps over N (32 cols each)
    int row0 = blockIdx.x * 128;
    if (tid < 128) sBias[tid] = bias[tid];

    float c[4][4][4];
#pragma unroll
    for (int mt = 0; mt < 4; mt++)
#pragma unroll
        for (int nt = 0; nt < 4; nt++)
#pragma unroll
            for (int r = 0; r < 4; r++) c[mt][nt][r] = 0.f;

    for (int ch = 0; ch < 4; ch++) {
        const float* srcA = ((ch < 2) ? g_agg : xin) + (ch & 1) * 64;
        const float* srcW = (ch < 2) ? wl : wr;
        int kw = (ch & 1) * 64;
        __syncthreads();
        // A tile: 128 rows x 64 k -> fragment-order smem
#pragma unroll
        for (int i = 0; i < 8; i++) {
            int idx = tid + i * 256;         // 0..2047
            int r = idx >> 4, q = idx & 15;  // row, float4-col (k=4q)
            int rg = row0 + r;
            float4 v = make_float4(0.f, 0.f, 0.f, 0.f);
            if (rg < N_NODES) v = *(const float4*)(srcA + (size_t)rg * 128 + q * 4);
            int mt = r >> 4, g = r & 7, hm = (r >> 3) & 1;
            int k8 = q >> 1, hk = q & 1;
            float* p = sA + (((mt * 8 + k8) * 32 + g * 4) * 4) + (hm + 2 * hk);
            p[0]  = f2tf32f(v.x);
            p[4]  = f2tf32f(v.y);
            p[8]  = f2tf32f(v.z);
            p[12] = f2tf32f(v.w);
        }
        // B tile: w[n][k] (row-major) -> col-major fragment-order smem
#pragma unroll
        for (int i = 0; i < 8; i++) {
            int idx = tid + i * 256;
            int n = idx >> 4, q = idx & 15;
            float4 v = *(const float4*)(srcW + (size_t)n * 128 + kw + q * 4);
            int nt = n >> 3, gN = n & 7;
            int k8 = q >> 1, regB = q & 1;
            float* p = sB + (((nt * 8 + k8) * 32 + gN * 4) * 2) + regB;
            p[0] = f2tf32f(v.x);
            p[2] = f2tf32f(v.y);
            p[4] = f2tf32f(v.z);
            p[6] = f2tf32f(v.w);
        }
        __syncthreads();
#pragma unroll
        for (int k8 = 0; k8 < 8; k8++) {
            uint32_t a[4][4], b[4][2];
#pragma unroll
            for (int mt = 0; mt < 4; mt++)
                *(uint4*)a[mt] = *(const uint4*)
                    (sA + ((((warp_m * 4 + mt) * 8 + k8) * 32 + lane) * 4));
#pragma unroll
            for (int nt = 0; nt < 4; nt++)
                *(uint2*)b[nt] = *(const uint2*)
                    (sB + ((((warp_n * 4 + nt) * 8 + k8) * 32 + lane) * 2));
#pragma unroll
            for (int mt = 0; mt < 4; mt++)
#pragma unroll
                for (int nt = 0; nt < 4; nt++)
                    mma_tf32(c[mt][nt], a[mt], b[nt]);
        }
    }

    // epilogue: bias + relu, fragment scatter
    int g = lane >> 2, tg = lane & 3;
#pragma unroll
    for (int mt = 0; mt < 4; mt++) {
        int row = row0 + warp_m * 64 + mt * 16 + g;
#pragma unroll
        for (int nt = 0; nt < 4; nt++) {
            int col = warp_n * 32 + nt * 8 + tg * 2;
            float b0 = sBias[col], b1 = sBias[col + 1];
            if (row < N_NODES) {
                float2 o;
                o.x = fmaxf(c[mt][nt][0] + b0, 0.f);
                o.y = fmaxf(c[mt][nt][1] + b1, 0.f);
                *(float2*)(out + (size_t)row * 128 + col) = o;
            }
            if (row + 8 < N_NODES) {
                float2 o;
                o.x = fmaxf(c[mt][nt][2] + b0, 0.f);
                o.y = fmaxf(c[mt][nt][3] + b1, 0.f);
                *(float2*)(out + (size_t)(row + 8) * 128 + col) = o;
            }
        }
    }
}

// ---------------- global mean pool (sum via red.v4) -------------------------
__global__ void k_pool(const int* __restrict__ batch) {
    int w = (blockIdx.x * blockDim.x + threadIdx.x) >> 5;
    int lane = threadIdx.x & 31;
    if (w >= N_NODES) return;
    int g = batch[w];
    float4 v = *(const float4*)(g_x0 + (size_t)w * HID + lane * 4);
    red_add_v4(g_gsum + (size_t)g * HID + lane * 4, v);
}

// ---------------- final linear head -----------------------------------------
__global__ void k_out(const float* __restrict__ wout, const float* __restrict__ bout,
                      float* __restrict__ y) {
    int g = blockIdx.x;
    __shared__ float row[128];
    float inv = 1.0f / fmaxf(g_gcnt[g], 1.0f);
    row[threadIdx.x] = g_gsum[g * 128 + threadIdx.x] * inv;
    __syncthreads();
    if (threadIdx.x < N_CLS) {
        float s = bout[threadIdx.x];
        const float* wrow = wout + threadIdx.x * 128;
#pragma unroll 16
        for (int d = 0; d < 128; d++) s += row[d] * wrow[d];
        y[g * N_CLS + threadIdx.x] = s;
    }
}

// ---------------- launch -----------------------------------------------------
extern "C" void kernel_launch(void* const* d_in, const int* in_sizes, int n_in,
                              void* d_out, int out_size) {
    const int*   x_tokens = (const int*)  d_in[0];
    const int*   ei       = (const int*)  d_in[1];
    const int*   batch    = (const int*)  d_in[2];
    const float* emb      = (const float*)d_in[3];
    const float* w1l      = (const float*)d_in[4];
    const float* b1       = (const float*)d_in[5];
    const float* w1r      = (const float*)d_in[6];
    const float* w2l      = (const float*)d_in[7];
    const float* b2       = (const float*)d_in[8];
    const float* w2r      = (const float*)d_in[9];
    const float* wout     = (const float*)d_in[10];
    const float* bout     = (const float*)d_in[11];
    float* y = (float*)d_out;

    const int* src = ei;
    const int* dst = ei + N_EDGES;

    cudaFuncSetAttribute(k_mm_mma, cudaFuncAttributeMaxDynamicSharedMemorySize,
                         MM_SMEM);

    float* p_x0;  cudaGetSymbolAddress((void**)&p_x0,  g_x0);
    float* p_h1;  cudaGetSymbolAddress((void**)&p_h1,  g_h1);

    k_zero_pre<<<512, 256>>>();
    k_embed  <<<(N_NODES * 32 + 255) / 256, 256>>>(x_tokens, emb);
    k_counts <<<(N_EDGES + 255) / 256, 256>>>(dst, batch);
    k_scan_a <<<NBLK, 256>>>();
    k_scan_b <<<1, 256>>>();
    k_scan_c <<<NBLK, 256>>>();
    k_fill   <<<(N_EDGES + 255) / 256, 256>>>(src, dst);

    int mm_grid = (N_NODES + 127) / 128;   // 391
    k_gather <<<(N_NODES * 32 + 255) / 256, 256>>>(0);
    k_mm_mma <<<mm_grid, 256, MM_SMEM>>>(p_x0, w1l, w1r, b1, p_h1);

    k_gather <<<(N_NODES * 32 + 255) / 256, 256>>>(1);
    k_mm_mma <<<mm_grid, 256, MM_SMEM>>>(p_h1, w2l, w2r, b2, p_x0);

    k_pool   <<<(N_NODES * 32 + 255) / 256, 256>>>(batch);
    k_out    <<<N_GRAPHS, 128>>>(wout, bout, y);
}

// round 7
// speedup vs baseline: 1.8474x; 1.1453x over previous
#include <cuda_runtime.h>
#include <cuda_fp16.h>
#include <cstdint>

#define N_NODES  50000
#define N_EDGES  600000
#define BAG      16
#define VOCAB    10000
#define EMB      128
#define HID      128
#define N_GRAPHS 512
#define N_CLS    10
#define PAD_IDX  1
#define NBLK 196   // ceil(N_NODES/256)

// ---------------- scratch (static device globals; no allocation) ------------
__device__ __align__(16) __half g_x16 [N_NODES * HID];  // embed out / features
__device__ __align__(16) __half g_h16 [N_NODES * HID];  // layer1 out
__device__ __align__(16) __half g_agg16[N_NODES * HID]; // neighbor mean
__device__ __align__(16) float  g_xf  [N_NODES * HID];  // layer2 out (fp32, pool)
__device__ __align__(16) __half g_tab16[VOCAB * EMB];   // fp16 emb table
__device__ __align__(16) float g_gsum[N_GRAPHS * HID];
__device__ __align__(16) float g_gcnt[N_GRAPHS];
// CSR
__device__ int g_degi  [N_NODES];
__device__ int g_offs  [N_NODES];
__device__ int g_cursor[N_NODES];
__device__ int g_adj   [N_EDGES];
__device__ int g_bsum  [256];
__device__ int g_bbase [256];

// ---------------- PTX helpers -----------------------------------------------
__device__ __forceinline__ void red_add_v4(float* p, float4 v) {
    asm volatile("red.global.add.v4.f32 [%0], {%1,%2,%3,%4};"
                 :: "l"(p), "f"(v.x), "f"(v.y), "f"(v.z), "f"(v.w) : "memory");
}
__device__ __forceinline__ float f2tf32f(float x) {
    uint32_t r; asm("cvt.rna.tf32.f32 %0, %1;" : "=r"(r) : "f"(x));
    return __uint_as_float(r);
}
__device__ __forceinline__ void mma_tf32(float* c, const uint32_t* a, const uint32_t* b) {
    asm volatile("mma.sync.aligned.m16n8k8.row.col.f32.tf32.tf32.f32 "
        "{%0,%1,%2,%3}, {%4,%5,%6,%7}, {%8,%9}, {%0,%1,%2,%3};"
        : "+f"(c[0]), "+f"(c[1]), "+f"(c[2]), "+f"(c[3])
        : "r"(a[0]), "r"(a[1]), "r"(a[2]), "r"(a[3]), "r"(b[0]), "r"(b[1]));
}
// load 4 halves at p (8B aligned) -> 4 floats
__device__ __forceinline__ float4 ld_h4(const __half* p) {
    uint2 u = *(const uint2*)p;
    __half2 h0 = *(__half2*)&u.x, h1 = *(__half2*)&u.y;
    float2 f0 = __half22float2(h0), f1 = __half22float2(h1);
    return make_float4(f0.x, f0.y, f1.x, f1.y);
}
__device__ __forceinline__ void st_h4(__half* p, float4 v) {
    uint2 u;
    *(__half2*)&u.x = __floats2half2_rn(v.x, v.y);
    *(__half2*)&u.y = __floats2half2_rn(v.z, v.w);
    *(uint2*)p = u;
}

// ---------------- zeroing + table prep --------------------------------------
__global__ void k_zero_pre(const float* __restrict__ table) {
    int t = blockIdx.x * blockDim.x + threadIdx.x;
    int stride = gridDim.x * blockDim.x;
    for (int i = t; i < N_NODES; i += stride) { g_degi[i] = 0; g_cursor[i] = 0; }
    for (int i = t; i < N_GRAPHS; i += stride) g_gcnt[i] = 0.f;
    for (int i = t; i < N_GRAPHS * HID; i += stride) g_gsum[i] = 0.f;
    for (int i = t; i < VOCAB * EMB / 4; i += stride) {
        float4 v = ((const float4*)table)[i];
        st_h4(g_tab16 + i * 4, v);
    }
}

// ---------------- embedding bag (mean, pad-excluded count) ------------------
__global__ void k_embed(const int* __restrict__ tokens) {
    int w = (blockIdx.x * blockDim.x + threadIdx.x) >> 5;
    int lane = threadIdx.x & 31;
    if (w >= N_NODES) return;
    const int* tk = tokens + w * BAG;
    float4 acc = make_float4(0.f, 0.f, 0.f, 0.f);
    int cnt = 0;
#pragma unroll
    for (int t = 0; t < BAG; t++) {
        int tok = tk[t];
        if (tok != PAD_IDX) {
            cnt++;
            float4 e = ld_h4(g_tab16 + (size_t)tok * EMB + lane * 4);
            acc.x += e.x; acc.y += e.y; acc.z += e.z; acc.w += e.w;
        }
    }
    float inv = 1.0f / (float)max(cnt, 1);
    acc.x *= inv; acc.y *= inv; acc.z *= inv; acc.w *= inv;
    st_h4(g_x16 + (size_t)w * HID + lane * 4, acc);
}

// ---------------- degree (int) + graph counts -------------------------------
__global__ void k_counts(const int* __restrict__ dst, const int* __restrict__ batch) {
    int i = blockIdx.x * blockDim.x + threadIdx.x;
    if (i < N_EDGES) atomicAdd(&g_degi[dst[i]], 1);
    if (i < N_NODES) atomicAdd(&g_gcnt[batch[i]], 1.0f);
}

// ---------------- 3-step exclusive scan of g_degi -> g_offs ------------------
__global__ void k_scan_a() {
    __shared__ int s[256];
    int t = threadIdx.x, i = blockIdx.x * 256 + t;
    int v = (i < N_NODES) ? g_degi[i] : 0;
    s[t] = v; __syncthreads();
#pragma unroll
    for (int o = 128; o > 0; o >>= 1) {
        if (t < o) s[t] += s[t + o];
        __syncthreads();
    }
    if (t == 0) g_bsum[blockIdx.x] = s[0];
}
__global__ void k_scan_b() {
    __shared__ int s[256];
    int t = threadIdx.x;
    int v = (t < NBLK) ? g_bsum[t] : 0;
    s[t] = v; __syncthreads();
#pragma unroll
    for (int o = 1; o < 256; o <<= 1) {
        int x = (t >= o) ? s[t - o] : 0;
        __syncthreads();
        s[t] += x;
        __syncthreads();
    }
    g_bbase[t] = s[t] - v;
}
__global__ void k_scan_c() {
    __shared__ int s[256];
    int t = threadIdx.x, i = blockIdx.x * 256 + t;
    int v = (i < N_NODES) ? g_degi[i] : 0;
    s[t] = v; __syncthreads();
#pragma unroll
    for (int o = 1; o < 256; o <<= 1) {
        int x = (t >= o) ? s[t - o] : 0;
        __syncthreads();
        s[t] += x;
        __syncthreads();
    }
    if (i < N_NODES) g_offs[i] = g_bbase[blockIdx.x] + s[t] - v;
}

// ---------------- CSR fill ---------------------------------------------------
__global__ void k_fill(const int* __restrict__ src, const int* __restrict__ dst) {
    int i = blockIdx.x * blockDim.x + threadIdx.x;
    if (i >= N_EDGES) return;
    int d = dst[i];
    int pos = atomicAdd(&g_cursor[d], 1);
    g_adj[g_offs[d] + pos] = src[i];
}

// ---------------- gather aggregation: agg[n] = mean_{s in N(n)} x[s] --------
__global__ void k_gather(int phase) {
    const __half* __restrict__ x = phase ? g_h16 : g_x16;
    int w = (blockIdx.x * blockDim.x + threadIdx.x) >> 5;
    int lane = threadIdx.x & 31;
    if (w >= N_NODES) return;
    int beg = g_offs[w];
    int d   = g_degi[w];
    float4 acc0 = make_float4(0.f, 0.f, 0.f, 0.f);
    float4 acc1 = make_float4(0.f, 0.f, 0.f, 0.f);
    int i = 0;
    for (; i + 2 <= d; i += 2) {
        int s0 = g_adj[beg + i], s1 = g_adj[beg + i + 1];
        float4 v0 = ld_h4(x + (size_t)s0 * HID + lane * 4);
        float4 v1 = ld_h4(x + (size_t)s1 * HID + lane * 4);
        acc0.x += v0.x; acc0.y += v0.y; acc0.z += v0.z; acc0.w += v0.w;
        acc1.x += v1.x; acc1.y += v1.y; acc1.z += v1.z; acc1.w += v1.w;
    }
    if (i < d) {
        int s0 = g_adj[beg + i];
        float4 v0 = ld_h4(x + (size_t)s0 * HID + lane * 4);
        acc0.x += v0.x; acc0.y += v0.y; acc0.z += v0.z; acc0.w += v0.w;
    }
    float inv = 1.0f / (float)max(d, 1);
    float4 o;
    o.x = (acc0.x + acc1.x) * inv;
    o.y = (acc0.y + acc1.y) * inv;
    o.z = (acc0.z + acc1.z) * inv;
    o.w = (acc0.w + acc1.w) * inv;
    st_h4(g_agg16 + (size_t)w * HID + lane * 4, o);
}

// ---------------- tf32 mma.sync fused dual GEMM + bias + relu ---------------
// out = relu( [agg | xin] @ [wl | wr]^T + bias ), K=256, 128x128 CTA tile
// A/xin are fp16 (exact in tf32); B converted fp32->tf32 at smem store.
#define MM_SMEM (65536 + 512)

__global__ __launch_bounds__(256) void k_mm_mma(const __half* __restrict__ xin,
                                                const float* __restrict__ wl,
                                                const float* __restrict__ wr,
                                                const float* __restrict__ bias,
                                                float* __restrict__ out32,
                                                __half* __restrict__ out16,
                                                int fp16out) {
    extern __shared__ float sm[];
    float* sA = sm;                 // A fragments (8192 floats)
    float* sB = sm + 8192;          // B fragments (8192 floats)
    float* sBias = sm + 16384;
    int tid = threadIdx.x;
    int lane = tid & 31, wid = tid >> 5;
    int warp_m = wid & 1;           // 2 warps over M (64 rows each)
    int warp_n = wid >> 1;          // 4 warps over N (32 cols each)
    int row0 = blockIdx.x * 128;
    if (tid < 128) sBias[tid] = bias[tid];

    float c[4][4][4];
#pragma unroll
    for (int mt = 0; mt < 4; mt++)
#pragma unroll
        for (int nt = 0; nt < 4; nt++)
#pragma unroll
            for (int r = 0; r < 4; r++) c[mt][nt][r] = 0.f;

    for (int ch = 0; ch < 4; ch++) {
        const __half* srcA = ((ch < 2) ? g_agg16 : xin) + (ch & 1) * 64;
        const float* srcW = (ch < 2) ? wl : wr;
        int kw = (ch & 1) * 64;
        __syncthreads();
        // A tile: 128 rows x 64 k (fp16 -> tf32 exact) -> fragment-order smem
#pragma unroll
        for (int i = 0; i < 8; i++) {
            int idx = tid + i * 256;         // 0..2047
            int r = idx >> 4, q = idx & 15;  // row, 4-elem k-group
            int rg = row0 + r;
            float4 v = make_float4(0.f, 0.f, 0.f, 0.f);
            if (rg < N_NODES) v = ld_h4(srcA + (size_t)rg * 128 + q * 4);
            int mt = r >> 4, g = r & 7, hm = (r >> 3) & 1;
            int k8 = q >> 1, hk = q & 1;
            float* p = sA + (((mt * 8 + k8) * 32 + g * 4) * 4) + (hm + 2 * hk);
            p[0]  = v.x;
            p[4]  = v.y;
            p[8]  = v.z;
            p[12] = v.w;
        }
        // B tile: w[n][k] (row-major fp32) -> col-major fragment-order smem
#pragma unroll
        for (int i = 0; i < 8; i++) {
            int idx = tid + i * 256;
            int n = idx >> 4, q = idx & 15;
            float4 v = *(const float4*)(srcW + (size_t)n * 128 + kw + q * 4);
            int nt = n >> 3, gN = n & 7;
            int k8 = q >> 1, regB = q & 1;
            float* p = sB + (((nt * 8 + k8) * 32 + gN * 4) * 2) + regB;
            p[0] = f2tf32f(v.x);
            p[2] = f2tf32f(v.y);
            p[4] = f2tf32f(v.z);
            p[6] = f2tf32f(v.w);
        }
        __syncthreads();
#pragma unroll
        for (int k8 = 0; k8 < 8; k8++) {
            uint32_t a[4][4], b[4][2];
#pragma unroll
            for (int mt = 0; mt < 4; mt++)
                *(uint4*)a[mt] = *(const uint4*)
                    (sA + ((((warp_m * 4 + mt) * 8 + k8) * 32 + lane) * 4));
#pragma unroll
            for (int nt = 0; nt < 4; nt++)
                *(uint2*)b[nt] = *(const uint2*)
                    (sB + ((((warp_n * 4 + nt) * 8 + k8) * 32 + lane) * 2));
#pragma unroll
            for (int mt = 0; mt < 4; mt++)
#pragma unroll
                for (int nt = 0; nt < 4; nt++)
                    mma_tf32(c[mt][nt], a[mt], b[nt]);
        }
    }

    // epilogue: bias + relu, fragment scatter
    int g = lane >> 2, tg = lane & 3;
#pragma unroll
    for (int mt = 0; mt < 4; mt++) {
        int row = row0 + warp_m * 64 + mt * 16 + g;
#pragma unroll
        for (int nt = 0; nt < 4; nt++) {
            int col = warp_n * 32 + nt * 8 + tg * 2;
            float b0 = sBias[col], b1 = sBias[col + 1];
            float r0x = fmaxf(c[mt][nt][0] + b0, 0.f);
            float r0y = fmaxf(c[mt][nt][1] + b1, 0.f);
            float r1x = fmaxf(c[mt][nt][2] + b0, 0.f);
            float r1y = fmaxf(c[mt][nt][3] + b1, 0.f);
            if (fp16out) {
                if (row < N_NODES)
                    *(__half2*)(out16 + (size_t)row * 128 + col) = __floats2half2_rn(r0x, r0y);
                if (row + 8 < N_NODES)
                    *(__half2*)(out16 + (size_t)(row + 8) * 128 + col) = __floats2half2_rn(r1x, r1y);
            } else {
                if (row < N_NODES)
                    *(float2*)(out32 + (size_t)row * 128 + col) = make_float2(r0x, r0y);
                if (row + 8 < N_NODES)
                    *(float2*)(out32 + (size_t)(row + 8) * 128 + col) = make_float2(r1x, r1y);
            }
        }
    }
}

// ---------------- global mean pool (sum via red.v4) -------------------------
__global__ void k_pool(const int* __restrict__ batch) {
    int w = (blockIdx.x * blockDim.x + threadIdx.x) >> 5;
    int lane = threadIdx.x & 31;
    if (w >= N_NODES) return;
    int g = batch[w];
    float4 v = *(const float4*)(g_xf + (size_t)w * HID + lane * 4);
    red_add_v4(g_gsum + (size_t)g * HID + lane * 4, v);
}

// ---------------- final linear head -----------------------------------------
__global__ void k_out(const float* __restrict__ wout, const float* __restrict__ bout,
                      float* __restrict__ y) {
    int g = blockIdx.x;
    __shared__ float row[128];
    float inv = 1.0f / fmaxf(g_gcnt[g], 1.0f);
    row[threadIdx.x] = g_gsum[g * 128 + threadIdx.x] * inv;
    __syncthreads();
    if (threadIdx.x < N_CLS) {
        float s = bout[threadIdx.x];
        const float* wrow = wout + threadIdx.x * 128;
#pragma unroll 16
        for (int d = 0; d < 128; d++) s += row[d] * wrow[d];
        y[g * N_CLS + threadIdx.x] = s;
    }
}

// ---------------- launch -----------------------------------------------------
extern "C" void kernel_launch(void* const* d_in, const int* in_sizes, int n_in,
                              void* d_out, int out_size) {
    const int*   x_tokens = (const int*)  d_in[0];
    const int*   ei       = (const int*)  d_in[1];
    const int*   batch    = (const int*)  d_in[2];
    const float* emb      = (const float*)d_in[3];
    const float* w1l      = (const float*)d_in[4];
    const float* b1       = (const float*)d_in[5];
    const float* w1r      = (const float*)d_in[6];
    const float* w2l      = (const float*)d_in[7];
    const float* b2       = (const float*)d_in[8];
    const float* w2r      = (const float*)d_in[9];
    const float* wout     = (const float*)d_in[10];
    const float* bout     = (const float*)d_in[11];
    float* y = (float*)d_out;

    const int* src = ei;
    const int* dst = ei + N_EDGES;

    cudaFuncSetAttribute(k_mm_mma, cudaFuncAttributeMaxDynamicSharedMemorySize,
                         MM_SMEM);

    __half* p_x16;  cudaGetSymbolAddress((void**)&p_x16, g_x16);
    __half* p_h16;  cudaGetSymbolAddress((void**)&p_h16, g_h16);
    float*  p_xf;   cudaGetSymbolAddress((void**)&p_xf,  g_xf);

    k_zero_pre<<<1024, 256>>>(emb);
    k_embed  <<<(N_NODES * 32 + 255) / 256, 256>>>(x_tokens);
    k_counts <<<(N_EDGES + 255) / 256, 256>>>(dst, batch);
    k_scan_a <<<NBLK, 256>>>();
    k_scan_b <<<1, 256>>>();
    k_scan_c <<<NBLK, 256>>>();
    k_fill   <<<(N_EDGES + 255) / 256, 256>>>(src, dst);

    int mm_grid = (N_NODES + 127) / 128;   // 391
    k_gather <<<(N_NODES * 32 + 255) / 256, 256>>>(0);
    k_mm_mma <<<mm_grid, 256, MM_SMEM>>>(p_x16, w1l, w1r, b1, nullptr, p_h16, 1);

    k_gather <<<(N_NODES * 32 + 255) / 256, 256>>>(1);
    k_mm_mma <<<mm_grid, 256, MM_SMEM>>>(p_h16, w2l, w2r, b2, p_xf, nullptr, 0);

    k_pool   <<<(N_NODES * 32 + 255) / 256, 256>>>(batch);
    k_out    <<<N_GRAPHS, 128>>>(wout, bout, y);
}

// round 8
// speedup vs baseline: 2.2900x; 1.2395x over previous
#include <cuda_runtime.h>
#include <cuda_fp16.h>
#include <cstdint>

#define N_NODES  50000
#define N_EDGES  600000
#define BAG      16
#define VOCAB    10000
#define EMB      128
#define HID      128
#define N_GRAPHS 512
#define N_CLS    10
#define PAD_IDX  1
#define NBLK 196   // ceil(N_NODES/256)

typedef unsigned long long ull;

// ---------------- scratch (static device globals; no allocation) ------------
__device__ __align__(16) __half g_x16 [N_NODES * HID];  // embed out / features
__device__ __align__(16) __half g_h16 [N_NODES * HID];  // layer1 out
__device__ __align__(16) __half g_agg16[N_NODES * HID]; // neighbor mean
__device__ __align__(16) float  g_xf  [N_NODES * HID];  // layer2 out (fp32, pool)
__device__ __align__(16) __half g_tab16[VOCAB * EMB];   // fp16 emb table
__device__ __align__(16) float g_gsum[N_GRAPHS * HID];
__device__ __align__(16) float g_gcnt[N_GRAPHS];
// CSR
__device__ int g_degi  [N_NODES];
__device__ int g_offs  [N_NODES];
__device__ int g_cursor[N_NODES];
__device__ int g_adj   [N_EDGES];
__device__ ull g_sstate[NBLK];     // decoupled-lookback state

// ---------------- helpers ----------------------------------------------------
__device__ __forceinline__ void red_add_v4(float* p, float4 v) {
    asm volatile("red.global.add.v4.f32 [%0], {%1,%2,%3,%4};"
                 :: "l"(p), "f"(v.x), "f"(v.y), "f"(v.z), "f"(v.w) : "memory");
}
__device__ __forceinline__ void mma_f16(float* c, const uint32_t* a, const uint32_t* b) {
    asm volatile("mma.sync.aligned.m16n8k16.row.col.f32.f16.f16.f32 "
        "{%0,%1,%2,%3}, {%4,%5,%6,%7}, {%8,%9}, {%0,%1,%2,%3};"
        : "+f"(c[0]), "+f"(c[1]), "+f"(c[2]), "+f"(c[3])
        : "r"(a[0]), "r"(a[1]), "r"(a[2]), "r"(a[3]), "r"(b[0]), "r"(b[1]));
}
__device__ __forceinline__ float4 ld_h4(const __half* p) {
    uint2 u = *(const uint2*)p;
    __half2 h0 = *(__half2*)&u.x, h1 = *(__half2*)&u.y;
    float2 f0 = __half22float2(h0), f1 = __half22float2(h1);
    return make_float4(f0.x, f0.y, f1.x, f1.y);
}
__device__ __forceinline__ void st_h4(__half* p, float4 v) {
    uint2 u;
    *(__half2*)&u.x = __floats2half2_rn(v.x, v.y);
    *(__half2*)&u.y = __floats2half2_rn(v.z, v.w);
    *(uint2*)p = u;
}

// ---------------- zeroing + table prep --------------------------------------
__global__ void k_zero_pre(const float* __restrict__ table) {
    int t = blockIdx.x * blockDim.x + threadIdx.x;
    int stride = gridDim.x * blockDim.x;
    for (int i = t; i < N_NODES; i += stride) { g_degi[i] = 0; g_cursor[i] = 0; }
    for (int i = t; i < N_GRAPHS; i += stride) g_gcnt[i] = 0.f;
    for (int i = t; i < N_GRAPHS * HID; i += stride) g_gsum[i] = 0.f;
    for (int i = t; i < NBLK; i += stride) g_sstate[i] = 0ull;
    for (int i = t; i < VOCAB * EMB / 4; i += stride) {
        float4 v = ((const float4*)table)[i];
        st_h4(g_tab16 + i * 4, v);
    }
}

// ---------------- embedding bag (mean, pad-excluded count) ------------------
__global__ void k_embed(const int* __restrict__ tokens) {
    int w = (blockIdx.x * blockDim.x + threadIdx.x) >> 5;
    int lane = threadIdx.x & 31;
    if (w >= N_NODES) return;
    const int* tk = tokens + w * BAG;
    float4 acc = make_float4(0.f, 0.f, 0.f, 0.f);
    int cnt = 0;
#pragma unroll
    for (int t = 0; t < BAG; t++) {
        int tok = tk[t];
        if (tok != PAD_IDX) {
            cnt++;
            float4 e = ld_h4(g_tab16 + (size_t)tok * EMB + lane * 4);
            acc.x += e.x; acc.y += e.y; acc.z += e.z; acc.w += e.w;
        }
    }
    float inv = 1.0f / (float)max(cnt, 1);
    acc.x *= inv; acc.y *= inv; acc.z *= inv; acc.w *= inv;
    st_h4(g_x16 + (size_t)w * HID + lane * 4, acc);
}

// ---------------- degree (int) + graph counts -------------------------------
__global__ void k_counts(const int* __restrict__ dst, const int* __restrict__ batch) {
    int i = blockIdx.x * blockDim.x + threadIdx.x;
    if (i < N_EDGES) atomicAdd(&g_degi[dst[i]], 1);
    if (i < N_NODES) atomicAdd(&g_gcnt[batch[i]], 1.0f);
}

// ---------------- single-kernel exclusive scan (decoupled lookback) ----------
__global__ void k_scan() {
    __shared__ int s[256];
    __shared__ ull run_sh;
    int t = threadIdx.x, bid = blockIdx.x;
    int i = bid * 256 + t;
    int v = (i < N_NODES) ? g_degi[i] : 0;
    s[t] = v; __syncthreads();
#pragma unroll
    for (int o = 1; o < 256; o <<= 1) {
        int x = (t >= o) ? s[t - o] : 0;
        __syncthreads();
        s[t] += x;
        __syncthreads();
    }
    int incl = s[t];
    int total = s[255];
    if (t == 0) {
        ull st = ((ull)(bid == 0 ? 2 : 1) << 32) | (unsigned)total;
        atomicExch(&g_sstate[bid], st);
    }
    if (t < 32) {
        ull run = 0;
        if (bid > 0) {
            int look = bid - 1;
            while (true) {
                int j = look - t;
                ull val; int stt;
                if (j >= 0) {
                    do { val = atomicAdd(&g_sstate[j], 0ull); stt = (int)(val >> 32); }
                    while (stt == 0);
                } else { val = (2ull << 32); stt = 2; }
                unsigned m = __ballot_sync(0xffffffffu, stt == 2);
                ull contrib;
                if (m) {
                    int first = __ffs(m) - 1;
                    contrib = (t <= first) ? (val & 0xffffffffull) : 0ull;
                } else {
                    contrib = val & 0xffffffffull;
                }
#pragma unroll
                for (int off = 16; off; off >>= 1)
                    contrib += __shfl_down_sync(0xffffffffu, contrib, off);
                contrib = __shfl_sync(0xffffffffu, contrib, 0);
                run += contrib;
                if (m) break;
                look -= 32;
            }
        }
        if (t == 0) {
            run_sh = run;
            if (bid > 0)
                atomicExch(&g_sstate[bid],
                           (2ull << 32) | (unsigned)(run + (ull)total));
        }
    }
    __syncthreads();
    if (i < N_NODES) g_offs[i] = (int)run_sh + incl - v;
}

// ---------------- CSR fill ---------------------------------------------------
__global__ void k_fill(const int* __restrict__ src, const int* __restrict__ dst) {
    int i = blockIdx.x * blockDim.x + threadIdx.x;
    if (i >= N_EDGES) return;
    int d = dst[i];
    int pos = atomicAdd(&g_cursor[d], 1);
    g_adj[g_offs[d] + pos] = src[i];
}

// ---------------- gather aggregation: agg[n] = mean_{s in N(n)} x[s] --------
__global__ void k_gather(int phase) {
    const __half* __restrict__ x = phase ? g_h16 : g_x16;
    int w = (blockIdx.x * blockDim.x + threadIdx.x) >> 5;
    int lane = threadIdx.x & 31;
    if (w >= N_NODES) return;
    int beg = g_offs[w];
    int d   = g_degi[w];
    float4 acc0 = make_float4(0.f, 0.f, 0.f, 0.f);
    float4 acc1 = make_float4(0.f, 0.f, 0.f, 0.f);
    int i = 0;
    for (; i + 2 <= d; i += 2) {
        int s0 = g_adj[beg + i], s1 = g_adj[beg + i + 1];
        float4 v0 = ld_h4(x + (size_t)s0 * HID + lane * 4);
        float4 v1 = ld_h4(x + (size_t)s1 * HID + lane * 4);
        acc0.x += v0.x; acc0.y += v0.y; acc0.z += v0.z; acc0.w += v0.w;
        acc1.x += v1.x; acc1.y += v1.y; acc1.z += v1.z; acc1.w += v1.w;
    }
    if (i < d) {
        int s0 = g_adj[beg + i];
        float4 v0 = ld_h4(x + (size_t)s0 * HID + lane * 4);
        acc0.x += v0.x; acc0.y += v0.y; acc0.z += v0.z; acc0.w += v0.w;
    }
    float inv = 1.0f / (float)max(d, 1);
    float4 o;
    o.x = (acc0.x + acc1.x) * inv;
    o.y = (acc0.y + acc1.y) * inv;
    o.z = (acc0.z + acc1.z) * inv;
    o.w = (acc0.w + acc1.w) * inv;
    st_h4(g_agg16 + (size_t)w * HID + lane * 4, o);
}

// ---------------- fp16 mma.sync fused dual GEMM + bias + relu ---------------
// out = relu( [agg | xin] @ [wl | wr]^T + bias ), K=256, 128x128 CTA tile
// sA: 8 mt x 4 k16 x 32 lanes x uint4 (16KB); sB: 16 nt x 4 k16 x 32 x uint2 (16KB)
#define MM_SMEM (32768 + 512)

__global__ __launch_bounds__(256) void k_mm_mma(const __half* __restrict__ xin,
                                                const float* __restrict__ wl,
                                                const float* __restrict__ wr,
                                                const float* __restrict__ bias,
                                                float* __restrict__ out32,
                                                __half* __restrict__ out16,
                                                int fp16out) {
    extern __shared__ uint32_t smu[];
    uint32_t* sA = smu;                 // 4096 u32
    uint32_t* sB = smu + 4096;          // 4096 u32
    float* sBias = (float*)(smu + 8192);
    int tid = threadIdx.x;
    int lane = tid & 31, wid = tid >> 5;
    int warp_m = wid & 1;           // 2 warps over M (64 rows each)
    int warp_n = wid >> 1;          // 4 warps over N (32 cols each)
    int row0 = blockIdx.x * 128;
    if (tid < 128) sBias[tid] = bias[tid];

    float c[4][4][4];
#pragma unroll
    for (int mt = 0; mt < 4; mt++)
#pragma unroll
        for (int nt = 0; nt < 4; nt++)
#pragma unroll
            for (int r = 0; r < 4; r++) c[mt][nt][r] = 0.f;

    for (int ch = 0; ch < 4; ch++) {
        const __half* srcA = ((ch < 2) ? g_agg16 : xin) + (ch & 1) * 64;
        const float* srcW = (ch < 2) ? wl : wr;
        int kw = (ch & 1) * 64;
        __syncthreads();
        // A tile: 128 rows x 64 k fp16 -> fragment-order smem (16B loads)
#pragma unroll
        for (int i = 0; i < 4; i++) {
            int idx = tid + i * 256;         // 0..1023
            int r = idx >> 3, q = idx & 7;   // row, 8-half group
            int rg = row0 + r;
            uint4 u = make_uint4(0u, 0u, 0u, 0u);
            if (rg < N_NODES)
                u = *(const uint4*)(srcA + (size_t)rg * 128 + q * 8);
            int mt = r >> 4, ri = r & 15;
            int k16 = q >> 1;
            int reg = (ri >= 8 ? 1 : 0) + 2 * (q & 1);
            uint32_t base = ((mt * 4 + k16) * 32) * 4 + reg;
            uint32_t lb = (ri & 7) * 16;     // lane*4 in u32 units
            sA[base + lb +  0] = u.x;
            sA[base + lb +  4] = u.y;
            sA[base + lb +  8] = u.z;
            sA[base + lb + 12] = u.w;
        }
        // B tile: w[n][k] fp32 -> fp16 fragment-order smem
#pragma unroll
        for (int i = 0; i < 8; i++) {
            int idx = tid + i * 256;         // 0..2047
            int n = idx >> 4, q = idx & 15;  // out-col, float4 group
            float4 v = *(const float4*)(srcW + (size_t)n * 128 + kw + q * 4);
            uint32_t h0, h1;
            *(__half2*)&h0 = __floats2half2_rn(v.x, v.y);   // kp = 2q
            *(__half2*)&h1 = __floats2half2_rn(v.z, v.w);   // kp = 2q+1
            int nt = n >> 3;
            int k16 = q >> 2;
            int reg = (q >> 1) & 1;
            int l0 = (n & 7) * 4 + 2 * (q & 1);
            uint32_t base = ((nt * 4 + k16) * 32) * 2 + reg;
            sB[base + l0 * 2]       = h0;
            sB[base + (l0 + 1) * 2] = h1;
        }
        __syncthreads();
#pragma unroll
        for (int k16 = 0; k16 < 4; k16++) {
            uint32_t a[4][4], b[4][2];
#pragma unroll
            for (int mt = 0; mt < 4; mt++)
                *(uint4*)a[mt] = *(const uint4*)
                    (sA + (((warp_m * 4 + mt) * 4 + k16) * 32 + lane) * 4);
#pragma unroll
            for (int nt = 0; nt < 4; nt++)
                *(uint2*)b[nt] = *(const uint2*)
                    (sB + (((warp_n * 4 + nt) * 4 + k16) * 32 + lane) * 2);
#pragma unroll
            for (int mt = 0; mt < 4; mt++)
#pragma unroll
                for (int nt = 0; nt < 4; nt++)
                    mma_f16(c[mt][nt], a[mt], b[nt]);
        }
    }

    // epilogue: bias + relu, fragment scatter
    int g = lane >> 2, tg = lane & 3;
#pragma unroll
    for (int mt = 0; mt < 4; mt++) {
        int row = row0 + warp_m * 64 + mt * 16 + g;
#pragma unroll
        for (int nt = 0; nt < 4; nt++) {
            int col = warp_n * 32 + nt * 8 + tg * 2;
            float b0 = sBias[col], b1 = sBias[col + 1];
            float r0x = fmaxf(c[mt][nt][0] + b0, 0.f);
            float r0y = fmaxf(c[mt][nt][1] + b1, 0.f);
            float r1x = fmaxf(c[mt][nt][2] + b0, 0.f);
            float r1y = fmaxf(c[mt][nt][3] + b1, 0.f);
            if (fp16out) {
                if (row < N_NODES)
                    *(__half2*)(out16 + (size_t)row * 128 + col) = __floats2half2_rn(r0x, r0y);
                if (row + 8 < N_NODES)
                    *(__half2*)(out16 + (size_t)(row + 8) * 128 + col) = __floats2half2_rn(r1x, r1y);
            } else {
                if (row < N_NODES)
                    *(float2*)(out32 + (size_t)row * 128 + col) = make_float2(r0x, r0y);
                if (row + 8 < N_NODES)
                    *(float2*)(out32 + (size_t)(row + 8) * 128 + col) = make_float2(r1x, r1y);
            }
        }
    }
}

// ---------------- global mean pool (sum via red.v4) -------------------------
__global__ void k_pool(const int* __restrict__ batch) {
    int w = (blockIdx.x * blockDim.x + threadIdx.x) >> 5;
    int lane = threadIdx.x & 31;
    if (w >= N_NODES) return;
    int g = batch[w];
    float4 v = *(const float4*)(g_xf + (size_t)w * HID + lane * 4);
    red_add_v4(g_gsum + (size_t)g * HID + lane * 4, v);
}

// ---------------- final linear head -----------------------------------------
__global__ void k_out(const float* __restrict__ wout, const float* __restrict__ bout,
                      float* __restrict__ y) {
    int g = blockIdx.x;
    __shared__ float row[128];
    float inv = 1.0f / fmaxf(g_gcnt[g], 1.0f);
    row[threadIdx.x] = g_gsum[g * 128 + threadIdx.x] * inv;
    __syncthreads();
    if (threadIdx.x < N_CLS) {
        float s = bout[threadIdx.x];
        const float* wrow = wout + threadIdx.x * 128;
#pragma unroll 16
        for (int d = 0; d < 128; d++) s += row[d] * wrow[d];
        y[g * N_CLS + threadIdx.x] = s;
    }
}

// ---------------- launch -----------------------------------------------------
extern "C" void kernel_launch(void* const* d_in, const int* in_sizes, int n_in,
                              void* d_out, int out_size) {
    const int*   x_tokens = (const int*)  d_in[0];
    const int*   ei       = (const int*)  d_in[1];
    const int*   batch    = (const int*)  d_in[2];
    const float* emb      = (const float*)d_in[3];
    const float* w1l      = (const float*)d_in[4];
    const float* b1       = (const float*)d_in[5];
    const float* w1r      = (const float*)d_in[6];
    const float* w2l      = (const float*)d_in[7];
    const float* b2       = (const float*)d_in[8];
    const float* w2r      = (const float*)d_in[9];
    const float* wout     = (const float*)d_in[10];
    const float* bout     = (const float*)d_in[11];
    float* y = (float*)d_out;

    const int* src = ei;
    const int* dst = ei + N_EDGES;

    cudaFuncSetAttribute(k_mm_mma, cudaFuncAttributeMaxDynamicSharedMemorySize,
                         MM_SMEM);

    __half* p_x16;  cudaGetSymbolAddress((void**)&p_x16, g_x16);
    __half* p_h16;  cudaGetSymbolAddress((void**)&p_h16, g_h16);
    float*  p_xf;   cudaGetSymbolAddress((void**)&p_xf,  g_xf);

    k_zero_pre<<<1024, 256>>>(emb);
    k_embed  <<<(N_NODES * 32 + 255) / 256, 256>>>(x_tokens);
    k_counts <<<(N_EDGES + 255) / 256, 256>>>(dst, batch);
    k_scan   <<<NBLK, 256>>>();
    k_fill   <<<(N_EDGES + 255) / 256, 256>>>(src, dst);

    int mm_grid = (N_NODES + 127) / 128;   // 391
    k_gather <<<(N_NODES * 32 + 255) / 256, 256>>>(0);
    k_mm_mma <<<mm_grid, 256, MM_SMEM>>>(p_x16, w1l, w1r, b1, nullptr, p_h16, 1);

    k_gather <<<(N_NODES * 32 + 255) / 256, 256>>>(1);
    k_mm_mma <<<mm_grid, 256, MM_SMEM>>>(p_h16, w2l, w2r, b2, p_xf, nullptr, 0);

    k_pool   <<<(N_NODES * 32 + 255) / 256, 256>>>(batch);
    k_out    <<<N_GRAPHS, 128>>>(wout, bout, y);
}